// round 11
// baseline (speedup 1.0000x reference)
#include <cuda_runtime.h>

// B=4096, N=64, H=16, FALLBACK=12
// grid (B,1,64,64) f32 | hints (B,2,64,16) f32 | w_g (1,64,64) | w_h (2,64,16)
// TWO warps per batch (rows 0..31 / 32..63). 1024 CTAs x 256 thr, 4 batches/CTA.
// Pair coupling: named barrier (64 threads). Col sums exchanged via smem.
// Fast path: sigmoid(3x)=0.5+0.5*tanh(1.5x), packed f32x2 FMAs.

static __global__ void zero_kernel(float* out) { out[0] = 0.0f; }

typedef unsigned long long u64;

__device__ __forceinline__ u64 pack2(float a, float b) {
    u64 r; asm("mov.b64 %0, {%1,%2};" : "=l"(r) : "f"(a), "f"(b)); return r;
}
__device__ __forceinline__ void unpack2(float& a, float& b, u64 v) {
    asm("mov.b64 {%0,%1}, %2;" : "=f"(a), "=f"(b) : "l"(v));
}
__device__ __forceinline__ void fma2(u64& d, u64 a, u64 b) {
    asm("fma.rn.f32x2 %0, %1, %2, %0;" : "+l"(d) : "l"(a), "l"(b));
}
__device__ __forceinline__ u64 mul2(u64 a, u64 b) {
    u64 r; asm("mul.rn.f32x2 %0, %1, %2;" : "=l"(r) : "l"(a), "l"(b)); return r;
}
__device__ __forceinline__ void add2(u64& d, u64 a) {
    asm("add.rn.f32x2 %0, %1, %0;" : "+l"(d) : "l"(a));
}
__device__ __forceinline__ float tanhf_fast(float x) {
    float y; asm("tanh.approx.f32 %0, %1;" : "=f"(y) : "f"(x)); return y;
}
__device__ __forceinline__ void bar_pair(int id) {
    asm volatile("bar.sync %0, 64;" :: "r"(id) : "memory");
}

#define NCTA 1024

__global__ void __launch_bounds__(256, 7) energy_kernel(
    const float* __restrict__ grid, const float* __restrict__ hints,
    const float* __restrict__ wg,   const float* __restrict__ wh,
    float* __restrict__ out)
{
    __shared__ float wgs[4096];        // w_g 16KB (only weight kept in smem)
    __shared__ float tgt[4 * 128];     // per-pair row/col targets
    __shared__ float colx[4][64];      // per-pair odd-warp col partials
    __shared__ int   slast[4][2];      // per-pair last_r,last_c
    __shared__ float wred[8];

    const int t    = threadIdx.x;
    const int wid  = t >> 5;
    const int l    = t & 31;
    const int pair = wid >> 1;         // 0..3 : batch within CTA
    const int half = wid & 1;          // 0: rows 0..31 + row hints; 1: rows 32..63 + col hints
    const int bar  = pair + 1;

    // One-time w_g preload (4 float4 per thread)
    {
        const float4* wgv = reinterpret_cast<const float4*>(wg);
        float4* wgsw = reinterpret_cast<float4*>(wgs);
        #pragma unroll
        for (int k = 0; k < 4; ++k) wgsw[k * 256 + t] = wgv[k * 256 + t];
    }
    __syncthreads();

    const int b = blockIdx.x * 4 + pair;
    const float4* hb  = reinterpret_cast<const float4*>(hints) + (size_t)b * 512;
    const float4* whv = reinterpret_cast<const float4*>(wh);
    float* mytgt = &tgt[pair * 128];

    // ---- Phase 1: hints, one plane per warp (8 float4 per lane) ----
    float s2p = 0.0f;
    int lastx = -1;                    // even: last_r ; odd: last_c
    #pragma unroll
    for (int k = 0; k < 8; ++k) {
        const int idx  = k * 32 + l;            // 0..255 within plane
        const int gidx = half * 256 + idx;
        float4 h = hb[gidx];
        float4 w = __ldg(&whv[gidx]);
        s2p += h.x * w.x + h.y * w.y + h.z * w.z + h.w * w.w;
        float part = (h.x + h.y) + (h.z + h.w);
        part += __shfl_xor_sync(0xffffffffu, part, 1);
        part += __shfl_xor_sync(0xffffffffu, part, 2);
        if ((l & 3) == 0) {
            const int hrow = idx >> 2;          // 0..63
            mytgt[half * 64 + hrow] = part;
            if (part > 0.0f) lastx = max(lastx, hrow);
        }
    }
    #pragma unroll
    for (int o = 16; o > 0; o >>= 1)
        lastx = max(lastx, __shfl_xor_sync(0xffffffffu, lastx, o));
    if (l == 0) slast[pair][half] = lastx;
    bar_pair(bar);                     // tgt + slast visible within pair

    int size;
    {
        int lr = slast[pair][0], lc = slast[pair][1];
        size = (lr >= 0 && lc >= 0) ? (max(lr, lc) + 1) : 12;
    }

    // ---- Phase 2: this warp's 32 rows = k in [half*16, half*16+16) ----
    const int c0    = (l & 15) << 2;
    const int rhalf = l >> 4;
    const int k0    = half * 16;
    const u64* gb2 = reinterpret_cast<const u64*>(grid) + (size_t)b * 2048;
    const u64* wg2 = reinterpret_cast<const u64*>(wgs);

    float s1p, binp, rerrp = 0.0f, cerrp = 0.0f;
    float pc0, pc1, pc2, pc3;

    if (size == 64) {
        const u64 c15 = pack2(1.5f, 1.5f);
        u64 s1 = 0ull, bin = 0ull, pcA = 0ull, pcB = 0ull;
        #pragma unroll 4
        for (int kk = 0; kk < 16; ++kk) {
            const int k  = k0 + kk;
            const int i2 = k * 64 + 2 * l;
            u64 g01 = gb2[i2], g23 = gb2[i2 + 1];
            u64 w01 = wg2[i2], w23 = wg2[i2 + 1];
            fma2(s1,  g01, w01);  fma2(s1,  g23, w23);
            fma2(bin, g01, g01);  fma2(bin, g23, g23);
            u64 a01 = mul2(g01, c15), a23 = mul2(g23, c15);
            float x0, x1, x2, x3;
            unpack2(x0, x1, a01); unpack2(x2, x3, a23);
            float t0 = tanhf_fast(x0), t1 = tanhf_fast(x1);
            float t2 = tanhf_fast(x2), t3 = tanhf_fast(x3);
            add2(pcA, pack2(t0, t1));
            add2(pcB, pack2(t2, t3));
            float tl = (t0 + t1) + (t2 + t3);
            tl += __shfl_xor_sync(0xffffffffu, tl, 1);
            tl += __shfl_xor_sync(0xffffffffu, tl, 2);
            tl += __shfl_xor_sync(0xffffffffu, tl, 4);
            tl += __shfl_xor_sync(0xffffffffu, tl, 8);
            if ((l & 15) == 0) {               // row sum = 32 + 0.5*T
                float d = fmaf(0.5f, tl, 32.0f - mytgt[2 * k + rhalf]);
                rerrp += d * d;
            }
        }
        float a, bq; unpack2(a, bq, s1);  s1p  = a + bq;
        unpack2(a, bq, bin);              binp = a + bq;
        unpack2(pc0, pc1, pcA); unpack2(pc2, pc3, pcB);
    } else {
        const float4* gb   = reinterpret_cast<const float4*>(grid) + (size_t)b * 1024;
        const float4* wgs4 = reinterpret_cast<const float4*>(wgs);
        s1p = 0.0f; binp = 0.0f;
        pc0 = 0.0f; pc1 = 0.0f; pc2 = 0.0f; pc3 = 0.0f;
        #pragma unroll 2
        for (int kk = 0; kk < 16; ++kk) {
            const int k   = k0 + kk;
            const int idx = k * 32 + l;
            const int r   = 2 * k + rhalf;
            float4 g = gb[idx];
            float4 w = wgs4[idx];
            s1p += g.x * w.x + g.y * w.y + g.z * w.z + g.w * w.w;
            const float rm = (r < size) ? 1.0f : 0.0f;
            float gx[4] = {g.x, g.y, g.z, g.w};
            float sg[4], pr = 0.0f;
            #pragma unroll
            for (int e = 0; e < 4; ++e) {
                float x = gx[e];
                sg[e] = __fdividef(1.0f, 1.0f + __expf(-3.0f * x)) * rm;
                if (c0 + e < size) {
                    pr   += sg[e];
                    binp += x * x * rm;
                }
            }
            pc0 += sg[0]; pc1 += sg[1]; pc2 += sg[2]; pc3 += sg[3];
            pr += __shfl_xor_sync(0xffffffffu, pr, 1);
            pr += __shfl_xor_sync(0xffffffffu, pr, 2);
            pr += __shfl_xor_sync(0xffffffffu, pr, 4);
            pr += __shfl_xor_sync(0xffffffffu, pr, 8);
            if ((l & 15) == 0 && r < size) {
                float d = pr - mytgt[r];
                rerrp += d * d;
            }
        }
    }

    // ---- Phase 3: column sums — fold 16-lane halves, then pair merge ----
    pc0 += __shfl_xor_sync(0xffffffffu, pc0, 16);
    pc1 += __shfl_xor_sync(0xffffffffu, pc1, 16);
    pc2 += __shfl_xor_sync(0xffffffffu, pc2, 16);
    pc3 += __shfl_xor_sync(0xffffffffu, pc3, 16);
    if (half == 1 && l < 16)
        *reinterpret_cast<float4*>(&colx[pair][c0]) = make_float4(pc0, pc1, pc2, pc3);
    bar_pair(bar);                     // odd partials visible to even warp

    if (half == 0 && l < 16) {
        float4 oc = *reinterpret_cast<const float4*>(&colx[pair][c0]);
        float cs[4] = {pc0 + oc.x, pc1 + oc.y, pc2 + oc.z, pc3 + oc.w};
        if (size == 64) {
            #pragma unroll
            for (int e = 0; e < 4; ++e) {
                float d = fmaf(0.5f, cs[e], 32.0f - mytgt[64 + c0 + e]);
                cerrp += d * d;
            }
        } else {
            #pragma unroll
            for (int e = 0; e < 4; ++e) {
                if (c0 + e < size) {
                    float d = cs[e] - mytgt[64 + c0 + e];
                    cerrp += d * d;
                }
            }
        }
    }

    // ---- Per-thread energy contribution; block reduce; one atomic/CTA ----
    const float inv = __fdividef(1.0f, (float)size);
    float local = s1p + s2p
                + 10.0f * inv * (rerrp + cerrp)
                + 0.1f  * inv * inv * binp;
    #pragma unroll
    for (int o = 16; o > 0; o >>= 1)
        local += __shfl_down_sync(0xffffffffu, local, o);
    if (l == 0) wred[wid] = local;
    __syncthreads();
    if (t < 32) {
        float v = (l < 8) ? wred[l] : 0.0f;
        v += __shfl_down_sync(0xffffffffu, v, 4);
        v += __shfl_down_sync(0xffffffffu, v, 2);
        v += __shfl_down_sync(0xffffffffu, v, 1);
        if (l == 0) atomicAdd(out, v * (1.0f / 4096.0f));
    }
}

extern "C" void kernel_launch(void* const* d_in, const int* in_sizes, int n_in,
                              void* d_out, int out_size) {
    const float* grid  = (const float*)d_in[0];
    const float* hints = (const float*)d_in[1];
    const float* wg    = (const float*)d_in[2];
    const float* wh    = (const float*)d_in[3];
    float* out = (float*)d_out;

    zero_kernel<<<1, 1>>>(out);
    energy_kernel<<<NCTA, 256>>>(grid, hints, wg, wh, out);
}

// round 14
// speedup vs baseline: 1.0515x; 1.0515x over previous
#include <cuda_runtime.h>
#include <cstdint>

// B=4096, N=64, H=16, FALLBACK=12
// grid (B,1,64,64) f32 | hints (B,2,64,16) f32 | w_g (1,64,64) | w_h (2,64,16)
// One warp per batch, data staged smem via cp.async.bulk + mbarrier.
// 148 CTAs x 256 thr, ~1 CTA/SM (220KB dyn smem), work-stealing.

__device__ int g_ctr;
static __global__ void zero_kernel(float* out) { out[0] = 0.0f; g_ctr = 0; }

typedef unsigned long long u64;

__device__ __forceinline__ u64 pack2(float a, float b) {
    u64 r; asm("mov.b64 %0, {%1,%2};" : "=l"(r) : "f"(a), "f"(b)); return r;
}
__device__ __forceinline__ void unpack2(float& a, float& b, u64 v) {
    asm("mov.b64 {%0,%1}, %2;" : "=f"(a), "=f"(b) : "l"(v));
}
__device__ __forceinline__ void fma2(u64& d, u64 a, u64 b) {
    asm("fma.rn.f32x2 %0, %1, %2, %0;" : "+l"(d) : "l"(a), "l"(b));
}
__device__ __forceinline__ u64 mul2(u64 a, u64 b) {
    u64 r; asm("mul.rn.f32x2 %0, %1, %2;" : "=l"(r) : "l"(a), "l"(b)); return r;
}
__device__ __forceinline__ void add2(u64& d, u64 a) {
    asm("add.rn.f32x2 %0, %1, %0;" : "+l"(d) : "l"(a));
}
__device__ __forceinline__ float tanhf_fast(float x) {
    float y; asm("tanh.approx.f32 %0, %1;" : "=f"(y) : "f"(x)); return y;
}
__device__ __forceinline__ uint32_t smem_u32(const void* p) {
    uint32_t a;
    asm("{ .reg .u64 t; cvta.to.shared.u64 t, %1; cvt.u32.u64 %0, t; }" : "=r"(a) : "l"(p));
    return a;
}
__device__ __forceinline__ void mbar_init(uint32_t mbar) {
    asm volatile("mbarrier.init.shared.b64 [%0], %1;" :: "r"(mbar), "r"(1u) : "memory");
}
__device__ __forceinline__ void mbar_expect(uint32_t mbar, uint32_t bytes) {
    asm volatile("mbarrier.arrive.expect_tx.shared.b64 _, [%0], %1;"
                 :: "r"(mbar), "r"(bytes) : "memory");
}
__device__ __forceinline__ void mbar_wait(uint32_t mbar, uint32_t phase) {
    asm volatile(
        "{\n\t.reg .pred P;\n"
        "WL%=:\n\t"
        "mbarrier.try_wait.parity.shared.b64 P, [%0], %1;\n\t"
        "@P bra.uni WD%=;\n\t"
        "bra.uni WL%=;\n"
        "WD%=:\n\t}"
        :: "r"(mbar), "r"(phase) : "memory");
}
__device__ __forceinline__ void bulk_cp(uint32_t dst, const void* src,
                                        uint32_t bytes, uint32_t mbar) {
    asm volatile(
        "cp.async.bulk.shared::cta.global.mbarrier::complete_tx::bytes [%0], [%1], %2, [%3];"
        :: "r"(dst), "l"(src), "r"(bytes), "r"(mbar) : "memory");
}

#define NB        4096
#define NCTA      148
// dynamic smem layout (bytes)
#define OFF_WGS   0                     // 16384
#define OFF_WHS   16384                 //  8192
#define OFF_MBAR  24576                 //    64 (8 x u64)
#define OFF_WRED  24640                 //    32
#define OFF_TGT   24672                 //  4096 (8 warps x 128 f)
#define OFF_BUF   28768                 //  8 x 24576
#define WSTRIDE   24576                 // per-warp: grid 16384 + hints 8192
#define SMEM_SZ   (28768 + 8 * 24576)   // 225376

__global__ void __launch_bounds__(256) energy_kernel(
    const float* __restrict__ grid, const float* __restrict__ hints,
    const float* __restrict__ wg,   const float* __restrict__ wh,
    float* __restrict__ out)
{
    extern __shared__ char smem[];
    float* wgs  = reinterpret_cast<float*>(smem + OFF_WGS);
    float* wred = reinterpret_cast<float*>(smem + OFF_WRED);

    const int t   = threadIdx.x;
    const int wid = t >> 5;
    const int l   = t & 31;

    // One-time weight preload into shared
    {
        const float4* wgv = reinterpret_cast<const float4*>(wg);
        const float4* whv = reinterpret_cast<const float4*>(wh);
        float4* wgsw = reinterpret_cast<float4*>(smem + OFF_WGS);
        float4* whsw = reinterpret_cast<float4*>(smem + OFF_WHS);
        #pragma unroll
        for (int k = 0; k < 4; ++k) wgsw[k * 256 + t] = wgv[k * 256 + t];
        #pragma unroll
        for (int k = 0; k < 2; ++k) whsw[k * 256 + t] = whv[k * 256 + t];
    }
    const uint32_t mbar = smem_u32(smem + OFF_MBAR) + wid * 8;
    if (l == 0) mbar_init(mbar);
    __syncthreads();                    // weights + mbar inits visible

    char* mybuf = smem + OFF_BUF + wid * WSTRIDE;         // grid 16K | hints 8K
    const uint32_t gdst = smem_u32(mybuf);
    const uint32_t hdst = gdst + 16384;
    float* mytgt = reinterpret_cast<float*>(smem + OFF_TGT) + wid * 128;
    const float4* whs4 = reinterpret_cast<const float4*>(smem + OFF_WHS);
    const u64*    wg2  = reinterpret_cast<const u64*>(smem + OFF_WGS);
    const float4* sgb4 = reinterpret_cast<const float4*>(mybuf);
    const u64*    sgb2 = reinterpret_cast<const u64*>(mybuf);
    const float4* shb4 = reinterpret_cast<const float4*>(mybuf + 16384);

    const int c0    = (l & 15) << 2;
    const int rhalf = l >> 4;
    uint32_t ph = 0;
    float acc = 0.0f;

    // Steal first batch, issue its copies
    int b;
    { int v = 0; if (l == 0) v = atomicAdd(&g_ctr, 1);
      b = __shfl_sync(0xffffffffu, v, 0); }
    if (b < NB && l == 0) {
        mbar_expect(mbar, 24576);
        bulk_cp(gdst, grid  + (size_t)b * 4096, 16384, mbar);
        bulk_cp(hdst, hints + (size_t)b * 2048,  8192, mbar);
    }

    while (b < NB) {
        mbar_wait(mbar, ph);
        ph ^= 1;

        // ---- Phase 1: hints from smem ----
        float s2p = 0.0f;
        int lastr = -1, lastc = -1;
        #pragma unroll
        for (int k = 0; k < 16; ++k) {
            const int idx = k * 32 + l;
            float4 h = shb4[idx];
            float4 w = whs4[idx];
            s2p += h.x * w.x + h.y * w.y + h.z * w.z + h.w * w.w;
            float part = (h.x + h.y) + (h.z + h.w);
            part += __shfl_xor_sync(0xffffffffu, part, 1);
            part += __shfl_xor_sync(0xffffffffu, part, 2);
            if ((l & 3) == 0) {
                const int hrow = (idx >> 2) & 63;
                mytgt[(k >> 3) * 64 + hrow] = part;
                if (part > 0.0f) {
                    if ((k >> 3) == 0) lastr = max(lastr, hrow);
                    else               lastc = max(lastc, hrow);
                }
            }
        }
        #pragma unroll
        for (int o = 16; o > 0; o >>= 1) {
            lastr = max(lastr, __shfl_xor_sync(0xffffffffu, lastr, o));
            lastc = max(lastc, __shfl_xor_sync(0xffffffffu, lastc, o));
        }
        const int size = (lastr >= 0 && lastc >= 0) ? (max(lastr, lastc) + 1) : 12;
        __syncwarp();

        // ---- Phase 2: grid from smem ----
        float s1p, binp, rerrp = 0.0f, cerrp = 0.0f;
        float pc0, pc1, pc2, pc3;

        if (size == 64) {
            const u64 c15 = pack2(1.5f, 1.5f);
            u64 s1 = 0ull, bin = 0ull, pcA = 0ull, pcB = 0ull;
            #pragma unroll 8
            for (int k = 0; k < 32; ++k) {
                const int i2 = k * 64 + 2 * l;
                u64 g01 = sgb2[i2], g23 = sgb2[i2 + 1];
                u64 w01 = wg2[i2],  w23 = wg2[i2 + 1];
                fma2(s1,  g01, w01);  fma2(s1,  g23, w23);
                fma2(bin, g01, g01);  fma2(bin, g23, g23);
                u64 a01 = mul2(g01, c15), a23 = mul2(g23, c15);
                float x0, x1, x2, x3;
                unpack2(x0, x1, a01); unpack2(x2, x3, a23);
                float t0 = tanhf_fast(x0), t1 = tanhf_fast(x1);
                float t2 = tanhf_fast(x2), t3 = tanhf_fast(x3);
                add2(pcA, pack2(t0, t1));
                add2(pcB, pack2(t2, t3));
                float tl = (t0 + t1) + (t2 + t3);
                tl += __shfl_xor_sync(0xffffffffu, tl, 1);
                tl += __shfl_xor_sync(0xffffffffu, tl, 2);
                tl += __shfl_xor_sync(0xffffffffu, tl, 4);
                tl += __shfl_xor_sync(0xffffffffu, tl, 8);
                if ((l & 15) == 0) {            // row sum = 32 + 0.5*T
                    float d = fmaf(0.5f, tl, 32.0f - mytgt[2 * k + rhalf]);
                    rerrp += d * d;
                }
            }
            float a, bq; unpack2(a, bq, s1);  s1p  = a + bq;
            unpack2(a, bq, bin);              binp = a + bq;
            unpack2(pc0, pc1, pcA); unpack2(pc2, pc3, pcB);
        } else {
            s1p = 0.0f; binp = 0.0f;
            pc0 = 0.0f; pc1 = 0.0f; pc2 = 0.0f; pc3 = 0.0f;
            const float4* wgs4 = reinterpret_cast<const float4*>(smem + OFF_WGS);
            #pragma unroll 4
            for (int k = 0; k < 32; ++k) {
                const int idx = k * 32 + l;
                const int r   = 2 * k + rhalf;
                float4 g = sgb4[idx];
                float4 w = wgs4[idx];
                s1p += g.x * w.x + g.y * w.y + g.z * w.z + g.w * w.w;
                const float rm = (r < size) ? 1.0f : 0.0f;
                float gx[4] = {g.x, g.y, g.z, g.w};
                float sg[4], pr = 0.0f;
                #pragma unroll
                for (int e = 0; e < 4; ++e) {
                    float x = gx[e];
                    sg[e] = __fdividef(1.0f, 1.0f + __expf(-3.0f * x)) * rm;
                    if (c0 + e < size) {
                        pr   += sg[e];
                        binp += x * x * rm;
                    }
                }
                pc0 += sg[0]; pc1 += sg[1]; pc2 += sg[2]; pc3 += sg[3];
                pr += __shfl_xor_sync(0xffffffffu, pr, 1);
                pr += __shfl_xor_sync(0xffffffffu, pr, 2);
                pr += __shfl_xor_sync(0xffffffffu, pr, 4);
                pr += __shfl_xor_sync(0xffffffffu, pr, 8);
                if ((l & 15) == 0 && r < size) {
                    float d = pr - mytgt[r];
                    rerrp += d * d;
                }
            }
        }

        // ---- Phase 3: column sums (fold halves in registers) ----
        pc0 += __shfl_xor_sync(0xffffffffu, pc0, 16);
        pc1 += __shfl_xor_sync(0xffffffffu, pc1, 16);
        pc2 += __shfl_xor_sync(0xffffffffu, pc2, 16);
        pc3 += __shfl_xor_sync(0xffffffffu, pc3, 16);
        if (l < 16) {
            float pcs[4] = {pc0, pc1, pc2, pc3};
            if (size == 64) {
                #pragma unroll
                for (int e = 0; e < 4; ++e) {
                    float d = fmaf(0.5f, pcs[e], 32.0f - mytgt[64 + c0 + e]);
                    cerrp += d * d;
                }
            } else {
                #pragma unroll
                for (int e = 0; e < 4; ++e) {
                    if (c0 + e < size) {
                        float d = pcs[e] - mytgt[64 + c0 + e];
                        cerrp += d * d;
                    }
                }
            }
        }

        const float inv = __fdividef(1.0f, (float)size);
        acc += s1p + s2p
             + 10.0f * inv * (rerrp + cerrp)
             + 0.1f  * inv * inv * binp;

        // ---- Steal next batch and refill buffer ----
        __syncwarp();                   // all lanes done reading this buffer
        int v = 0; if (l == 0) v = atomicAdd(&g_ctr, 1);
        int bn = __shfl_sync(0xffffffffu, v, 0);
        if (bn < NB && l == 0) {
            mbar_expect(mbar, 24576);
            bulk_cp(gdst, grid  + (size_t)bn * 4096, 16384, mbar);
            bulk_cp(hdst, hints + (size_t)bn * 2048,  8192, mbar);
        }
        b = bn;
    }

    // ---- Block reduction, one atomic per CTA ----
    #pragma unroll
    for (int o = 16; o > 0; o >>= 1)
        acc += __shfl_down_sync(0xffffffffu, acc, o);
    if (l == 0) wred[wid] = acc;
    __syncthreads();
    if (t < 32) {
        float v = (l < 8) ? wred[l] : 0.0f;
        v += __shfl_down_sync(0xffffffffu, v, 4);
        v += __shfl_down_sync(0xffffffffu, v, 2);
        v += __shfl_down_sync(0xffffffffu, v, 1);
        if (l == 0) atomicAdd(out, v * (1.0f / 4096.0f));
    }
}

extern "C" void kernel_launch(void* const* d_in, const int* in_sizes, int n_in,
                              void* d_out, int out_size) {
    const float* grid  = (const float*)d_in[0];
    const float* hints = (const float*)d_in[1];
    const float* wg    = (const float*)d_in[2];
    const float* wh    = (const float*)d_in[3];
    float* out = (float*)d_out;

    cudaFuncSetAttribute(energy_kernel,
                         cudaFuncAttributeMaxDynamicSharedMemorySize, SMEM_SZ);
    zero_kernel<<<1, 1>>>(out);
    energy_kernel<<<NCTA, 256, SMEM_SZ>>>(grid, hints, wg, wh, out);
}

// round 15
// speedup vs baseline: 1.3413x; 1.2755x over previous
#include <cuda_runtime.h>
#include <cstdint>

// B=4096, N=64, H=16, FALLBACK=12
// grid (B,1,64,64) f32 | hints (B,2,64,16) f32 | w_g (1,64,64) | w_h (2,64,16)
// CTA-per-batch: 4096 CTAs x 128 thr (4 warps per batch -> 1/4 chain length).
// Weights via __ldg (L1-hot), smem only for targets/col-merge (1.7KB).

static __global__ void zero_kernel(float* out) { out[0] = 0.0f; }

typedef unsigned long long u64;

__device__ __forceinline__ u64 pack2(float a, float b) {
    u64 r; asm("mov.b64 %0, {%1,%2};" : "=l"(r) : "f"(a), "f"(b)); return r;
}
__device__ __forceinline__ void unpack2(float& a, float& b, u64 v) {
    asm("mov.b64 {%0,%1}, %2;" : "=f"(a), "=f"(b) : "l"(v));
}
__device__ __forceinline__ void fma2(u64& d, u64 a, u64 b) {
    asm("fma.rn.f32x2 %0, %1, %2, %0;" : "+l"(d) : "l"(a), "l"(b));
}
__device__ __forceinline__ u64 mul2(u64 a, u64 b) {
    u64 r; asm("mul.rn.f32x2 %0, %1, %2;" : "=l"(r) : "l"(a), "l"(b)); return r;
}
__device__ __forceinline__ void add2(u64& d, u64 a) {
    asm("add.rn.f32x2 %0, %1, %0;" : "+l"(d) : "l"(a));
}
__device__ __forceinline__ float tanhf_fast(float x) {
    float y; asm("tanh.approx.f32 %0, %1;" : "=f"(y) : "f"(x)); return y;
}

__global__ void __launch_bounds__(128, 10) energy_kernel(
    const float* __restrict__ grid, const float* __restrict__ hints,
    const float* __restrict__ wg,   const float* __restrict__ wh,
    float* __restrict__ out)
{
    __shared__ float tgt[128];      // [0..63] row targets, [64..127] col targets
    __shared__ float colp[4][64];   // per-warp column partials
    __shared__ int   slast[2];
    __shared__ float wred[4];

    const int t   = threadIdx.x;
    const int wid = t >> 5;
    const int l   = t & 31;
    const int b   = blockIdx.x;

    if (t < 2) slast[t] = -1;
    __syncthreads();                            // #0: slast init visible

    // ---- Phase 1: hints. 4 float4 per thread; w_h via __ldg ----
    const float4* hb  = reinterpret_cast<const float4*>(hints) + (size_t)b * 512;
    const float4* whv = reinterpret_cast<const float4*>(wh);
    float s2p = 0.0f;
    int lastr = -1, lastc = -1;
    #pragma unroll
    for (int k = 0; k < 4; ++k) {
        const int idx = k * 128 + t;            // plane = k>>1, hr = (k&1)*32 + t>>2
        float4 h = hb[idx];
        float4 w = __ldg(&whv[idx]);
        s2p += h.x * w.x + h.y * w.y + h.z * w.z + h.w * w.w;
        float part = (h.x + h.y) + (h.z + h.w);
        part += __shfl_xor_sync(0xffffffffu, part, 1);
        part += __shfl_xor_sync(0xffffffffu, part, 2);
        if ((t & 3) == 0) {
            const int hr = ((k & 1) << 5) + (t >> 2);
            tgt[(k >> 1) * 64 + hr] = part;
            if (part > 0.0f) {
                if ((k >> 1) == 0) lastr = max(lastr, hr);
                else               lastc = max(lastc, hr);
            }
        }
    }
    #pragma unroll
    for (int o = 16; o > 0; o >>= 1) {
        lastr = max(lastr, __shfl_xor_sync(0xffffffffu, lastr, o));
        lastc = max(lastc, __shfl_xor_sync(0xffffffffu, lastc, o));
    }
    if (l == 0) {
        atomicMax(&slast[0], lastr);
        atomicMax(&slast[1], lastc);
    }
    __syncthreads();                            // #1: tgt + slast ready

    int size;
    {
        int lr = slast[0], lc = slast[1];
        size = (lr >= 0 && lc >= 0) ? (max(lr, lc) + 1) : 12;
    }

    // ---- Phase 2: grid, 8 float4 per thread. row = k*8 + (t>>4) ----
    const int c0 = (t & 15) << 2;
    const u64* gb2 = reinterpret_cast<const u64*>(grid) + (size_t)b * 2048;
    const u64* wg2 = reinterpret_cast<const u64*>(wg);

    float s1p, binp, rerrp = 0.0f, cerrp = 0.0f;
    float pc0, pc1, pc2, pc3;

    if (size == 64) {
        const u64 c15 = pack2(1.5f, 1.5f);
        u64 s1 = 0ull, bin = 0ull, pcA = 0ull, pcB = 0ull;
        #pragma unroll
        for (int k = 0; k < 8; ++k) {
            const int i2 = k * 256 + 2 * t;     // u64 index (2 per float4)
            u64 g01 = gb2[i2],          g23 = gb2[i2 + 1];
            u64 w01 = __ldg(wg2 + i2),  w23 = __ldg(wg2 + i2 + 1);
            fma2(s1,  g01, w01);  fma2(s1,  g23, w23);
            fma2(bin, g01, g01);  fma2(bin, g23, g23);
            u64 a01 = mul2(g01, c15), a23 = mul2(g23, c15);
            float x0, x1, x2, x3;
            unpack2(x0, x1, a01); unpack2(x2, x3, a23);
            float t0 = tanhf_fast(x0), t1 = tanhf_fast(x1);
            float t2 = tanhf_fast(x2), t3 = tanhf_fast(x3);
            add2(pcA, pack2(t0, t1));
            add2(pcB, pack2(t2, t3));
            float tl = (t0 + t1) + (t2 + t3);
            tl += __shfl_xor_sync(0xffffffffu, tl, 1);
            tl += __shfl_xor_sync(0xffffffffu, tl, 2);
            tl += __shfl_xor_sync(0xffffffffu, tl, 4);
            tl += __shfl_xor_sync(0xffffffffu, tl, 8);
            if ((l & 15) == 0) {                // row sum = 32 + 0.5*T
                float d = fmaf(0.5f, tl, 32.0f - tgt[k * 8 + (t >> 4)]);
                rerrp += d * d;
            }
        }
        float a, bq; unpack2(a, bq, s1);  s1p  = a + bq;
        unpack2(a, bq, bin);              binp = a + bq;
        unpack2(pc0, pc1, pcA); unpack2(pc2, pc3, pcB);
    } else {
        const float4* gb   = reinterpret_cast<const float4*>(grid) + (size_t)b * 1024;
        const float4* wgv4 = reinterpret_cast<const float4*>(wg);
        s1p = 0.0f; binp = 0.0f;
        pc0 = 0.0f; pc1 = 0.0f; pc2 = 0.0f; pc3 = 0.0f;
        #pragma unroll
        for (int k = 0; k < 8; ++k) {
            const int idx = k * 128 + t;
            const int r   = k * 8 + (t >> 4);
            float4 g = gb[idx];
            float4 w = __ldg(&wgv4[idx]);
            s1p += g.x * w.x + g.y * w.y + g.z * w.z + g.w * w.w;
            const float rm = (r < size) ? 1.0f : 0.0f;
            float gx[4] = {g.x, g.y, g.z, g.w};
            float sg[4], pr = 0.0f;
            #pragma unroll
            for (int e = 0; e < 4; ++e) {
                float x = gx[e];
                sg[e] = __fdividef(1.0f, 1.0f + __expf(-3.0f * x)) * rm;
                if (c0 + e < size) {
                    pr   += sg[e];
                    binp += x * x * rm;
                }
            }
            pc0 += sg[0]; pc1 += sg[1]; pc2 += sg[2]; pc3 += sg[3];
            pr += __shfl_xor_sync(0xffffffffu, pr, 1);
            pr += __shfl_xor_sync(0xffffffffu, pr, 2);
            pr += __shfl_xor_sync(0xffffffffu, pr, 4);
            pr += __shfl_xor_sync(0xffffffffu, pr, 8);
            if ((l & 15) == 0 && r < size) {
                float d = pr - tgt[r];
                rerrp += d * d;
            }
        }
    }

    // ---- Phase 3: column merge across 4 warps via 1KB smem ----
    pc0 += __shfl_xor_sync(0xffffffffu, pc0, 16);
    pc1 += __shfl_xor_sync(0xffffffffu, pc1, 16);
    pc2 += __shfl_xor_sync(0xffffffffu, pc2, 16);
    pc3 += __shfl_xor_sync(0xffffffffu, pc3, 16);
    if (l < 16)
        *reinterpret_cast<float4*>(&colp[wid][c0]) = make_float4(pc0, pc1, pc2, pc3);
    __syncthreads();                            // #2: colp ready

    if (t < 64) {
        float cs = colp[0][t] + colp[1][t] + colp[2][t] + colp[3][t];
        if (size == 64) {
            float d = fmaf(0.5f, cs, 32.0f - tgt[64 + t]);
            cerrp = d * d;
        } else if (t < size) {
            float d = cs - tgt[64 + t];
            cerrp = d * d;
        }
    }

    // ---- Energy + block reduction, one atomic per CTA ----
    const float inv = __fdividef(1.0f, (float)size);
    float local = s1p + s2p
                + 10.0f * inv * (rerrp + cerrp)
                + 0.1f  * inv * inv * binp;
    #pragma unroll
    for (int o = 16; o > 0; o >>= 1)
        local += __shfl_down_sync(0xffffffffu, local, o);
    if (l == 0) wred[wid] = local;
    __syncthreads();                            // #3
    if (t < 32) {
        float v = (l < 4) ? wred[l] : 0.0f;
        v += __shfl_down_sync(0xffffffffu, v, 2);
        v += __shfl_down_sync(0xffffffffu, v, 1);
        if (l == 0) atomicAdd(out, v * (1.0f / 4096.0f));
    }
}

extern "C" void kernel_launch(void* const* d_in, const int* in_sizes, int n_in,
                              void* d_out, int out_size) {
    const float* grid  = (const float*)d_in[0];
    const float* hints = (const float*)d_in[1];
    const float* wg    = (const float*)d_in[2];
    const float* wh    = (const float*)d_in[3];
    float* out = (float*)d_out;

    zero_kernel<<<1, 1>>>(out);
    energy_kernel<<<4096, 128>>>(grid, hints, wg, wh, out);
}

// round 16
// speedup vs baseline: 1.4465x; 1.0784x over previous
#include <cuda_runtime.h>
#include <cstdint>

// B=4096, N=64, H=16, FALLBACK=12
// grid (B,1,64,64) f32 | hints (B,2,64,16) f32 | w_g (1,64,64) | w_h (2,64,16)
// CTA-per-batch, 4096 x 128. Speculative unmasked streaming loop with NO shfl
// and NO barrier; one __syncthreads; errors assembled in epilogue from smem.

static __global__ void zero_kernel(float* out) { out[0] = 0.0f; }

typedef unsigned long long u64;

__device__ __forceinline__ u64 pack2(float a, float b) {
    u64 r; asm("mov.b64 %0, {%1,%2};" : "=l"(r) : "f"(a), "f"(b)); return r;
}
__device__ __forceinline__ void unpack2(float& a, float& b, u64 v) {
    asm("mov.b64 {%0,%1}, %2;" : "=f"(a), "=f"(b) : "l"(v));
}
__device__ __forceinline__ void fma2(u64& d, u64 a, u64 b) {
    asm("fma.rn.f32x2 %0, %1, %2, %0;" : "+l"(d) : "l"(a), "l"(b));
}
__device__ __forceinline__ u64 mul2(u64 a, u64 b) {
    u64 r; asm("mul.rn.f32x2 %0, %1, %2;" : "=l"(r) : "l"(a), "l"(b)); return r;
}
__device__ __forceinline__ void add2(u64& d, u64 a) {
    asm("add.rn.f32x2 %0, %1, %0;" : "+l"(d) : "l"(a));
}
__device__ __forceinline__ float tanhf_fast(float x) {
    float y; asm("tanh.approx.f32 %0, %1;" : "=f"(y) : "f"(x)); return y;
}

#define RP(r, g) rowp[(r) * 17 + (g)]

__global__ void __launch_bounds__(128, 9) energy_kernel(
    const float* __restrict__ grid, const float* __restrict__ hints,
    const float* __restrict__ wg,   const float* __restrict__ wh,
    float* __restrict__ out)
{
    __shared__ float rowp[64 * 17];   // per-(row, lanegroup) tanh partials
    __shared__ float tgt[128];        // [0..63] row targets, [64..127] col targets
    __shared__ float colp[4][64];     // per-warp column partials
    __shared__ int   slastr[4], slastc[4];
    __shared__ float wred[4];

    const int t   = threadIdx.x;
    const int wid = t >> 5;
    const int l   = t & 31;
    const int b   = blockIdx.x;
    const int g16 = t & 15;           // column group (cols g16*4 .. +3)

    // ================= Phase 1: hints (no barrier needed before grid) ======
    const float4* hb  = reinterpret_cast<const float4*>(hints) + (size_t)b * 512;
    const float4* whv = reinterpret_cast<const float4*>(wh);
    float s2p = 0.0f;
    int lastr = -1, lastc = -1;
    #pragma unroll
    for (int k = 0; k < 4; ++k) {
        const int idx = k * 128 + t;              // plane = k>>1
        float4 h = hb[idx];
        float4 w = __ldg(&whv[idx]);
        s2p += h.x * w.x + h.y * w.y + h.z * w.z + h.w * w.w;
        float part = (h.x + h.y) + (h.z + h.w);
        part += __shfl_xor_sync(0xffffffffu, part, 1);
        part += __shfl_xor_sync(0xffffffffu, part, 2);
        if ((t & 3) == 0) {
            const int hr = ((k & 1) << 5) + (t >> 2);
            tgt[(k >> 1) * 64 + hr] = part;
            if (part > 0.0f) {
                if ((k >> 1) == 0) lastr = max(lastr, hr);
                else               lastc = max(lastc, hr);
            }
        }
    }
    lastr = max(lastr, __shfl_xor_sync(0xffffffffu, lastr, 16));
    lastr = max(lastr, __shfl_xor_sync(0xffffffffu, lastr, 8));
    lastr = max(lastr, __shfl_xor_sync(0xffffffffu, lastr, 4));
    lastc = max(lastc, __shfl_xor_sync(0xffffffffu, lastc, 16));
    lastc = max(lastc, __shfl_xor_sync(0xffffffffu, lastc, 8));
    lastc = max(lastc, __shfl_xor_sync(0xffffffffu, lastc, 4));
    if (l == 0) { slastr[wid] = lastr; slastc[wid] = lastc; }

    // ================= Phase 2: speculative unmasked grid streaming ========
    // Loop body has NO shfl, NO barrier, NO size dependence: pure streaming.
    const int rbase = t >> 4;                     // 2*wid + (l>>4): rows k*8+rbase
    const u64* gb2 = reinterpret_cast<const u64*>(grid) + (size_t)b * 2048;
    const u64* wg2 = reinterpret_cast<const u64*>(wg);
    const u64 c15 = pack2(1.5f, 1.5f);
    u64 s1 = 0ull, bin = 0ull, pcA = 0ull, pcB = 0ull;
    #pragma unroll
    for (int k = 0; k < 8; ++k) {
        const int i2 = k * 256 + 2 * t;
        u64 g01 = gb2[i2],         g23 = gb2[i2 + 1];
        u64 w01 = __ldg(wg2 + i2), w23 = __ldg(wg2 + i2 + 1);
        fma2(s1,  g01, w01);  fma2(s1,  g23, w23);
        fma2(bin, g01, g01);  fma2(bin, g23, g23);
        u64 a01 = mul2(g01, c15), a23 = mul2(g23, c15);
        float x0, x1, x2, x3;
        unpack2(x0, x1, a01); unpack2(x2, x3, a23);
        float t0 = tanhf_fast(x0), t1 = tanhf_fast(x1);
        float t2 = tanhf_fast(x2), t3 = tanhf_fast(x3);
        add2(pcA, pack2(t0, t1));
        add2(pcB, pack2(t2, t3));
        RP(k * 8 + rbase, g16) = (t0 + t1) + (t2 + t3);   // deferred row reduce
    }
    float s1p, binp, pc0, pc1, pc2, pc3;
    { float a, q; unpack2(a, q, s1);  s1p  = a + q;
      unpack2(a, q, bin);             binp = a + q; }
    unpack2(pc0, pc1, pcA); unpack2(pc2, pc3, pcB);
    pc0 += __shfl_xor_sync(0xffffffffu, pc0, 16);
    pc1 += __shfl_xor_sync(0xffffffffu, pc1, 16);
    pc2 += __shfl_xor_sync(0xffffffffu, pc2, 16);
    pc3 += __shfl_xor_sync(0xffffffffu, pc3, 16);
    if (l < 16)
        *reinterpret_cast<float4*>(&colp[wid][g16 << 2]) =
            make_float4(pc0, pc1, pc2, pc3);

    __syncthreads();    // THE barrier: tgt, slast, rowp, colp all ready

    // ================= Epilogue ============================================
    const int lr = max(max(slastr[0], slastr[1]), max(slastr[2], slastr[3]));
    const int lc = max(max(slastc[0], slastc[1]), max(slastc[2], slastc[3]));
    const int size = (lr >= 0 && lc >= 0) ? (max(lr, lc) + 1) : 12;

    float errp = 0.0f;                // per-thread (row+col) error contribution

    if (size == 64) {                 // speculation correct (P ~ 1)
        if (t < 64) {
            float rs = 0.0f;
            #pragma unroll
            for (int j = 0; j < 16; ++j) rs += RP(t, j);
            float d  = fmaf(0.5f, rs, 32.0f - tgt[t]);       // row error
            float cs = colp[0][t] + colp[1][t] + colp[2][t] + colp[3][t];
            float d2 = fmaf(0.5f, cs, 32.0f - tgt[64 + t]);  // col error
            errp = d * d + d2 * d2;
        }
    } else {
        // Rare masked recompute: re-stream grid with exact masked sigmoid.
        const float4* gb = reinterpret_cast<const float4*>(grid) + (size_t)b * 1024;
        const int c0 = g16 << 2;
        float binm = 0.0f, rerrp = 0.0f;
        float q0 = 0.0f, q1 = 0.0f, q2 = 0.0f, q3 = 0.0f;
        #pragma unroll 2
        for (int k = 0; k < 8; ++k) {
            const int idx = k * 128 + t;
            const int r   = k * 8 + rbase;
            float4 g = gb[idx];
            const float rm = (r < size) ? 1.0f : 0.0f;
            float gx[4] = {g.x, g.y, g.z, g.w};
            float sg[4], pr = 0.0f;
            #pragma unroll
            for (int e = 0; e < 4; ++e) {
                float x = gx[e];
                sg[e] = __fdividef(1.0f, 1.0f + __expf(-3.0f * x)) * rm;
                if (c0 + e < size) {
                    pr   += sg[e];
                    binm += x * x * rm;
                }
            }
            q0 += sg[0]; q1 += sg[1]; q2 += sg[2]; q3 += sg[3];
            pr += __shfl_xor_sync(0xffffffffu, pr, 1);
            pr += __shfl_xor_sync(0xffffffffu, pr, 2);
            pr += __shfl_xor_sync(0xffffffffu, pr, 4);
            pr += __shfl_xor_sync(0xffffffffu, pr, 8);
            if ((l & 15) == 0 && r < size) {
                float d = pr - tgt[r];
                rerrp += d * d;
            }
        }
        binp = binm;                   // override speculative (unmasked) binp
        errp = rerrp;
        q0 += __shfl_xor_sync(0xffffffffu, q0, 16);
        q1 += __shfl_xor_sync(0xffffffffu, q1, 16);
        q2 += __shfl_xor_sync(0xffffffffu, q2, 16);
        q3 += __shfl_xor_sync(0xffffffffu, q3, 16);
        __syncthreads();               // uniform branch: safe
        if (l < 16)
            *reinterpret_cast<float4*>(&colp[wid][c0]) = make_float4(q0, q1, q2, q3);
        __syncthreads();
        if (t < size) {
            float cs = colp[0][t] + colp[1][t] + colp[2][t] + colp[3][t];
            float d = cs - tgt[64 + t];
            errp += d * d;
        }
    }

    // ================= Energy + block reduce, one atomic per CTA ===========
    const float inv = __fdividef(1.0f, (float)size);
    float local = s1p + s2p
                + 10.0f * inv * errp
                + 0.1f  * inv * inv * binp;
    #pragma unroll
    for (int o = 16; o > 0; o >>= 1)
        local += __shfl_down_sync(0xffffffffu, local, o);
    if (l == 0) wred[wid] = local;
    __syncthreads();
    if (t < 32) {
        float v = (l < 4) ? wred[l] : 0.0f;
        v += __shfl_down_sync(0xffffffffu, v, 2);
        v += __shfl_down_sync(0xffffffffu, v, 1);
        if (l == 0) atomicAdd(out, v * (1.0f / 4096.0f));
    }
}

extern "C" void kernel_launch(void* const* d_in, const int* in_sizes, int n_in,
                              void* d_out, int out_size) {
    const float* grid  = (const float*)d_in[0];
    const float* hints = (const float*)d_in[1];
    const float* wg    = (const float*)d_in[2];
    const float* wh    = (const float*)d_in[3];
    float* out = (float*)d_out;

    zero_kernel<<<1, 1>>>(out);
    energy_kernel<<<4096, 128>>>(grid, hints, wg, wh, out);
}

// round 17
// speedup vs baseline: 1.5983x; 1.1050x over previous
#include <cuda_runtime.h>
#include <cstdint>

// B=4096, N=64, H=16, FALLBACK=12
// grid (B,1,64,64) f32 | hints (B,2,64,16) f32 | w_g (1,64,64) | w_h (2,64,16)
// CTA-per-batch, 4096 x 128. Speculative unmasked streaming, one barrier,
// deferred reductions. This round: LDG.128 (double2) for grid+w_g halves the
// hot-loop load instruction count; halves feed fma.f32x2 as free u64 pairs.

static __global__ void zero_kernel(float* out) { out[0] = 0.0f; }

typedef unsigned long long u64;

__device__ __forceinline__ u64 pack2(float a, float b) {
    u64 r; asm("mov.b64 %0, {%1,%2};" : "=l"(r) : "f"(a), "f"(b)); return r;
}
__device__ __forceinline__ void unpack2(float& a, float& b, u64 v) {
    asm("mov.b64 {%0,%1}, %2;" : "=f"(a), "=f"(b) : "l"(v));
}
__device__ __forceinline__ void fma2(u64& d, u64 a, u64 b) {
    asm("fma.rn.f32x2 %0, %1, %2, %0;" : "+l"(d) : "l"(a), "l"(b));
}
__device__ __forceinline__ u64 mul2(u64 a, u64 b) {
    u64 r; asm("mul.rn.f32x2 %0, %1, %2;" : "=l"(r) : "l"(a), "l"(b)); return r;
}
__device__ __forceinline__ void add2(u64& d, u64 a) {
    asm("add.rn.f32x2 %0, %1, %0;" : "+l"(d) : "l"(a));
}
__device__ __forceinline__ float tanhf_fast(float x) {
    float y; asm("tanh.approx.f32 %0, %1;" : "=f"(y) : "f"(x)); return y;
}

#define RP(r, g) rowp[(r) * 17 + (g)]

__global__ void __launch_bounds__(128, 9) energy_kernel(
    const float* __restrict__ grid, const float* __restrict__ hints,
    const float* __restrict__ wg,   const float* __restrict__ wh,
    float* __restrict__ out)
{
    __shared__ float rowp[64 * 17];   // per-(row, lanegroup) tanh partials
    __shared__ float tgt[128];        // [0..63] row targets, [64..127] col targets
    __shared__ float colp[4][64];     // per-warp column partials
    __shared__ int   slastr[4], slastc[4];
    __shared__ float wred[4];

    const int t   = threadIdx.x;
    const int wid = t >> 5;
    const int l   = t & 31;
    const int b   = blockIdx.x;
    const int g16 = t & 15;           // column group (cols g16*4 .. +3)

    // ================= Phase 1: hints (no barrier before grid loop) ========
    const float4* hb  = reinterpret_cast<const float4*>(hints) + (size_t)b * 512;
    const float4* whv = reinterpret_cast<const float4*>(wh);
    float s2p = 0.0f;
    int lastr = -1, lastc = -1;
    #pragma unroll
    for (int k = 0; k < 4; ++k) {
        const int idx = k * 128 + t;              // plane = k>>1
        float4 h = hb[idx];
        float4 w = __ldg(&whv[idx]);
        s2p += h.x * w.x + h.y * w.y + h.z * w.z + h.w * w.w;
        float part = (h.x + h.y) + (h.z + h.w);
        part += __shfl_xor_sync(0xffffffffu, part, 1);
        part += __shfl_xor_sync(0xffffffffu, part, 2);
        if ((t & 3) == 0) {
            const int hr = ((k & 1) << 5) + (t >> 2);
            tgt[(k >> 1) * 64 + hr] = part;
            if (part > 0.0f) {
                if ((k >> 1) == 0) lastr = max(lastr, hr);
                else               lastc = max(lastc, hr);
            }
        }
    }
    lastr = max(lastr, __shfl_xor_sync(0xffffffffu, lastr, 16));
    lastr = max(lastr, __shfl_xor_sync(0xffffffffu, lastr, 8));
    lastr = max(lastr, __shfl_xor_sync(0xffffffffu, lastr, 4));
    lastc = max(lastc, __shfl_xor_sync(0xffffffffu, lastc, 16));
    lastc = max(lastc, __shfl_xor_sync(0xffffffffu, lastc, 8));
    lastc = max(lastc, __shfl_xor_sync(0xffffffffu, lastc, 4));
    if (l == 0) { slastr[wid] = lastr; slastc[wid] = lastc; }

    // ================= Phase 2: speculative streaming, LDG.128 =============
    const int rbase = t >> 4;                     // rows k*8 + rbase
    const double2* gb2 = reinterpret_cast<const double2*>(grid) + (size_t)b * 1024;
    const double2* wg2 = reinterpret_cast<const double2*>(wg);
    const u64 c15 = pack2(1.5f, 1.5f);
    u64 s1 = 0ull, bin = 0ull, pcA = 0ull, pcB = 0ull;
    #pragma unroll
    for (int k = 0; k < 8; ++k) {
        const int idx = k * 128 + t;              // one 16B load each
        double2 gd = gb2[idx];
        double2 wd = __ldg(&wg2[idx]);
        u64 g01 = __double_as_longlong(gd.x), g23 = __double_as_longlong(gd.y);
        u64 w01 = __double_as_longlong(wd.x), w23 = __double_as_longlong(wd.y);
        fma2(s1,  g01, w01);  fma2(s1,  g23, w23);
        fma2(bin, g01, g01);  fma2(bin, g23, g23);
        u64 a01 = mul2(g01, c15), a23 = mul2(g23, c15);
        float x0, x1, x2, x3;
        unpack2(x0, x1, a01); unpack2(x2, x3, a23);
        float t0 = tanhf_fast(x0), t1 = tanhf_fast(x1);
        float t2 = tanhf_fast(x2), t3 = tanhf_fast(x3);
        add2(pcA, pack2(t0, t1));
        add2(pcB, pack2(t2, t3));
        RP(k * 8 + rbase, g16) = (t0 + t1) + (t2 + t3);   // deferred row reduce
    }
    float s1p, binp, pc0, pc1, pc2, pc3;
    { float a, q; unpack2(a, q, s1);  s1p  = a + q;
      unpack2(a, q, bin);             binp = a + q; }
    unpack2(pc0, pc1, pcA); unpack2(pc2, pc3, pcB);
    pc0 += __shfl_xor_sync(0xffffffffu, pc0, 16);
    pc1 += __shfl_xor_sync(0xffffffffu, pc1, 16);
    pc2 += __shfl_xor_sync(0xffffffffu, pc2, 16);
    pc3 += __shfl_xor_sync(0xffffffffu, pc3, 16);
    if (l < 16)
        *reinterpret_cast<float4*>(&colp[wid][g16 << 2]) =
            make_float4(pc0, pc1, pc2, pc3);

    __syncthreads();    // THE barrier: tgt, slast, rowp, colp all ready

    // ================= Epilogue ============================================
    const int lr = max(max(slastr[0], slastr[1]), max(slastr[2], slastr[3]));
    const int lc = max(max(slastc[0], slastc[1]), max(slastc[2], slastc[3]));
    const int size = (lr >= 0 && lc >= 0) ? (max(lr, lc) + 1) : 12;

    float errp = 0.0f;

    if (size == 64) {                 // speculation correct (P ~ 1)
        if (t < 64) {
            float rs = 0.0f;
            #pragma unroll
            for (int j = 0; j < 16; ++j) rs += RP(t, j);
            float d  = fmaf(0.5f, rs, 32.0f - tgt[t]);       // row error
            float cs = colp[0][t] + colp[1][t] + colp[2][t] + colp[3][t];
            float d2 = fmaf(0.5f, cs, 32.0f - tgt[64 + t]);  // col error
            errp = d * d + d2 * d2;
        }
    } else {
        // Rare masked recompute with exact sigmoid (uniform branch).
        const float4* gb = reinterpret_cast<const float4*>(grid) + (size_t)b * 1024;
        const int c0 = g16 << 2;
        float binm = 0.0f, rerrp = 0.0f;
        float q0 = 0.0f, q1 = 0.0f, q2 = 0.0f, q3 = 0.0f;
        #pragma unroll 2
        for (int k = 0; k < 8; ++k) {
            const int idx = k * 128 + t;
            const int r   = k * 8 + rbase;
            float4 g = gb[idx];
            const float rm = (r < size) ? 1.0f : 0.0f;
            float gx[4] = {g.x, g.y, g.z, g.w};
            float sg[4], pr = 0.0f;
            #pragma unroll
            for (int e = 0; e < 4; ++e) {
                float x = gx[e];
                sg[e] = __fdividef(1.0f, 1.0f + __expf(-3.0f * x)) * rm;
                if (c0 + e < size) {
                    pr   += sg[e];
                    binm += x * x * rm;
                }
            }
            q0 += sg[0]; q1 += sg[1]; q2 += sg[2]; q3 += sg[3];
            pr += __shfl_xor_sync(0xffffffffu, pr, 1);
            pr += __shfl_xor_sync(0xffffffffu, pr, 2);
            pr += __shfl_xor_sync(0xffffffffu, pr, 4);
            pr += __shfl_xor_sync(0xffffffffu, pr, 8);
            if ((l & 15) == 0 && r < size) {
                float d = pr - tgt[r];
                rerrp += d * d;
            }
        }
        binp = binm;
        errp = rerrp;
        q0 += __shfl_xor_sync(0xffffffffu, q0, 16);
        q1 += __shfl_xor_sync(0xffffffffu, q1, 16);
        q2 += __shfl_xor_sync(0xffffffffu, q2, 16);
        q3 += __shfl_xor_sync(0xffffffffu, q3, 16);
        __syncthreads();
        if (l < 16)
            *reinterpret_cast<float4*>(&colp[wid][c0]) = make_float4(q0, q1, q2, q3);
        __syncthreads();
        if (t < size) {
            float cs = colp[0][t] + colp[1][t] + colp[2][t] + colp[3][t];
            float d = cs - tgt[64 + t];
            errp += d * d;
        }
    }

    // ================= Energy + block reduce, one atomic per CTA ===========
    const float inv = __fdividef(1.0f, (float)size);
    float local = s1p + s2p
                + 10.0f * inv * errp
                + 0.1f  * inv * inv * binp;
    #pragma unroll
    for (int o = 16; o > 0; o >>= 1)
        local += __shfl_down_sync(0xffffffffu, local, o);
    if (l == 0) wred[wid] = local;
    __syncthreads();
    if (t < 32) {
        float v = (l < 4) ? wred[l] : 0.0f;
        v += __shfl_down_sync(0xffffffffu, v, 2);
        v += __shfl_down_sync(0xffffffffu, v, 1);
        if (l == 0) atomicAdd(out, v * (1.0f / 4096.0f));
    }
}

extern "C" void kernel_launch(void* const* d_in, const int* in_sizes, int n_in,
                              void* d_out, int out_size) {
    const float* grid  = (const float*)d_in[0];
    const float* hints = (const float*)d_in[1];
    const float* wg    = (const float*)d_in[2];
    const float* wh    = (const float*)d_in[3];
    float* out = (float*)d_out;

    zero_kernel<<<1, 1>>>(out);
    energy_kernel<<<4096, 128>>>(grid, hints, wg, wh, out);
}